// round 13
// baseline (speedup 1.0000x reference)
#include <cuda_runtime.h>
#include <cuda_bf16.h>

// y[t, f] = x[t, f] * w[f] + b[f]
// x: [8192, 4096] f32 (128 MiB), w/b: [4096] f32, out: same shape.
//
// Pure HBM streaming. Measured ladder on sm_103a:
//  - LDG.128 optimal width (v8 loads tank L1tex). L2 games lose. .cs neutral.
//  - ILP ridge = 4 (36.1 / 35.3 / 39.8). Block 256 >= 512.
// This round: persistent grid-stride — 148 SMs x 8 CTAs, every warp slot busy
// start-to-finish, no wave transitions / CTA tail. Inner body = proven ILP=4
// split-quarter mapping.

#define TOKENS      8192
#define IN_FEATURES 4096
#define COLS4       (IN_FEATURES / 4)    // 1024, pow2
#define N4          (TOKENS * COLS4)     // 8,388,608 quads
#define Q4          (N4 / 4)             // 2,097,152 (multiple of COLS4)

#define NSM         148
#define CTAS_PER_SM 8
#define THREADS     256
#define GRID        (NSM * CTAS_PER_SM)  // 1184

__global__ __launch_bounds__(THREADS) void one_to_one_kernel(
    const float4* __restrict__ x,
    const float4* __restrict__ w,
    const float4* __restrict__ b,
    float4* __restrict__ out)
{
    const int stride = GRID * THREADS;               // 303,104
    for (int i = blockIdx.x * THREADS + threadIdx.x; i < Q4; i += stride) {
        int c = i & (COLS4 - 1);                     // same column for all 4 quads

        // Four independent streaming loads, front-batched for deep MLP
        float4 x0 = x[i];
        float4 x1 = x[i + Q4];
        float4 x2 = x[i + 2 * Q4];
        float4 x3 = x[i + 3 * Q4];

        float4 wv = __ldg(&w[c]);
        float4 bv = __ldg(&b[c]);

        float4 r0, r1, r2, r3;
        r0.x = fmaf(x0.x, wv.x, bv.x); r0.y = fmaf(x0.y, wv.y, bv.y);
        r0.z = fmaf(x0.z, wv.z, bv.z); r0.w = fmaf(x0.w, wv.w, bv.w);
        r1.x = fmaf(x1.x, wv.x, bv.x); r1.y = fmaf(x1.y, wv.y, bv.y);
        r1.z = fmaf(x1.z, wv.z, bv.z); r1.w = fmaf(x1.w, wv.w, bv.w);
        r2.x = fmaf(x2.x, wv.x, bv.x); r2.y = fmaf(x2.y, wv.y, bv.y);
        r2.z = fmaf(x2.z, wv.z, bv.z); r2.w = fmaf(x2.w, wv.w, bv.w);
        r3.x = fmaf(x3.x, wv.x, bv.x); r3.y = fmaf(x3.y, wv.y, bv.y);
        r3.z = fmaf(x3.z, wv.z, bv.z); r3.w = fmaf(x3.w, wv.w, bv.w);

        out[i]          = r0;
        out[i + Q4]     = r1;
        out[i + 2 * Q4] = r2;
        out[i + 3 * Q4] = r3;
    }
}

extern "C" void kernel_launch(void* const* d_in, const int* in_sizes, int n_in,
                              void* d_out, int out_size)
{
    const float4* x = (const float4*)d_in[0];
    const float4* w = (const float4*)d_in[1];
    const float4* b = (const float4*)d_in[2];
    float4* out = (float4*)d_out;

    one_to_one_kernel<<<GRID, THREADS>>>(x, w, b, out);
}

// round 14
// speedup vs baseline: 1.0839x; 1.0839x over previous
#include <cuda_runtime.h>
#include <cuda_bf16.h>

// y[t, f] = x[t, f] * w[f] + b[f]
// x: [8192, 4096] f32 (128 MiB), w/b: [4096] f32, out: same shape.
//
// Pure HBM streaming. Measured ladder on sm_103a:
//  - LDG.128 optimal width (v8 loads tank L1tex). ILP ridge = 4.
//  - Block 256 best. Persistent grid-stride loses (occ + serialized MLP).
//  - .cs on BOTH loads+stores: neutral (load-side hurt, store-side helped?).
// Effective BW (7.6 TB/s) > HBM BW (6.0 TB/s): ~20% of x reads already hit L2
// across graph replays. This round: asymmetric policy — default loads keep x
// L2-resident, st.global.cs (evict-first) stops the write stream from
// evicting x. One-variable change vs the 35.3us R8 winner.

#define TOKENS      8192
#define IN_FEATURES 4096
#define COLS4       (IN_FEATURES / 4)    // 1024, pow2
#define N4          (TOKENS * COLS4)     // 8,388,608 quads
#define Q4          (N4 / 4)             // 2,097,152 (multiple of COLS4)

__device__ __forceinline__ void stg_cs(float4* p, float4 v) {
    asm volatile("st.global.cs.v4.f32 [%0], {%1,%2,%3,%4};"
                 :: "l"(p), "f"(v.x), "f"(v.y), "f"(v.z), "f"(v.w)
                 : "memory");
}

__global__ __launch_bounds__(256) void one_to_one_kernel(
    const float4* __restrict__ x,
    const float4* __restrict__ w,
    const float4* __restrict__ b,
    float4* __restrict__ out)
{
    int i = blockIdx.x * blockDim.x + threadIdx.x;   // 0 .. Q4-1
    int c = i & (COLS4 - 1);                         // same column for all 4 quads

    // Four independent streaming loads (default policy: keep x in L2),
    // front-batched for deep MLP
    float4 x0 = x[i];
    float4 x1 = x[i + Q4];
    float4 x2 = x[i + 2 * Q4];
    float4 x3 = x[i + 3 * Q4];

    float4 wv = __ldg(&w[c]);
    float4 bv = __ldg(&b[c]);

    float4 r0, r1, r2, r3;
    r0.x = fmaf(x0.x, wv.x, bv.x); r0.y = fmaf(x0.y, wv.y, bv.y);
    r0.z = fmaf(x0.z, wv.z, bv.z); r0.w = fmaf(x0.w, wv.w, bv.w);
    r1.x = fmaf(x1.x, wv.x, bv.x); r1.y = fmaf(x1.y, wv.y, bv.y);
    r1.z = fmaf(x1.z, wv.z, bv.z); r1.w = fmaf(x1.w, wv.w, bv.w);
    r2.x = fmaf(x2.x, wv.x, bv.x); r2.y = fmaf(x2.y, wv.y, bv.y);
    r2.z = fmaf(x2.z, wv.z, bv.z); r2.w = fmaf(x2.w, wv.w, bv.w);
    r3.x = fmaf(x3.x, wv.x, bv.x); r3.y = fmaf(x3.y, wv.y, bv.y);
    r3.z = fmaf(x3.z, wv.z, bv.z); r3.w = fmaf(x3.w, wv.w, bv.w);

    // Evict-first stores: out is never re-read; don't churn x out of L2.
    stg_cs(&out[i],          r0);
    stg_cs(&out[i + Q4],     r1);
    stg_cs(&out[i + 2 * Q4], r2);
    stg_cs(&out[i + 3 * Q4], r3);
}

extern "C" void kernel_launch(void* const* d_in, const int* in_sizes, int n_in,
                              void* d_out, int out_size)
{
    const float4* x = (const float4*)d_in[0];
    const float4* w = (const float4*)d_in[1];
    const float4* b = (const float4*)d_in[2];
    float4* out = (float4*)d_out;

    const int threads = 256;
    const int blocks  = Q4 / threads;   // 8192
    one_to_one_kernel<<<blocks, threads>>>(x, w, b, out);
}